// round 9
// baseline (speedup 1.0000x reference)
#include <cuda_runtime.h>
#include <cstdint>

// CostVolume: out[b,d,h,x] = (1/128) * sum_c L[b,c,h,x]*R[b,c,h,x-d], x>=d else 0
// B=8 C=128 H=128 W=240 V=48
// R staged in smem (double-buffered cp.async); L streamed from global through
// a 2-stage register pipeline (8 channels/stage) so every LDG has a full
// compute stage between issue and use. Parity-phased x-pairing keeps all R
// operand pairs aligned (no pair-construction MOVs on the R side).
#define B_  8
#define C_  128
#define H_  128
#define W_  240
#define V_  48
#define HW_ (H_*W_)

#define CC   16            // channels per chunk (R smem tile rows)
#define NCH  (C_/CC)       // 8 chunks
#define THREADS 128
#define RW   288           // sR row width: 48 zero pad + 240 data

typedef unsigned long long ull;

__device__ __forceinline__ ull pk(float lo, float hi) {
    ull r; asm("mov.b64 %0, {%1, %2};" : "=l"(r) : "f"(lo), "f"(hi)); return r;
}
__device__ __forceinline__ void upk(ull v, float& lo, float& hi) {
    asm("mov.b64 {%0, %1}, %2;" : "=f"(lo), "=f"(hi) : "l"(v));
}
__device__ __forceinline__ void fma2(ull& acc, ull a, ull b) {
    asm("fma.rn.f32x2 %0, %1, %2, %0;" : "+l"(acc) : "l"(a), "l"(b));
}
__device__ __forceinline__ void cpasync16(uint32_t saddr, const void* g) {
    asm volatile("cp.async.cg.shared.global [%0], [%1], 16;" :: "r"(saddr), "l"(g));
}

__global__ void __launch_bounds__(THREADS, 2)
cv_kernel(const float* __restrict__ L, const float* __restrict__ R,
          float* __restrict__ out)
{
    extern __shared__ float sR[];     // [2][CC][RW]

    const int tid = threadIdx.x;
    const int h = blockIdx.x;
    const int b = blockIdx.y;

    const int xg = tid & 63;          // 0..63 (60 active)
    const int ig = tid >> 6;          // 0..1
    const int i0 = ig * 24;           // disparity base for this group
    const int xb = xg * 4;
    const bool act  = (xg < 60);
    const bool edge = (xg < 59);      // xb+4 valid

    const float* Lbase = L + ((size_t)b * C_ * H_ + h) * W_;
    const float* Rbase = R + ((size_t)b * C_ * H_ + h) * W_;

    // L register pipeline: two stages of 8 channels each.
    float4 LqA[8], LqB[8];
    float  LsA[8], LsB[8];

    // stage load: channels [cbase, cbase+8) -> (q, s)
    auto ldgL = [&](float4* q, float* s, int cbase) {
        #pragma unroll
        for (int k = 0; k < 8; k++) {
            const float* p = Lbase + (size_t)(cbase + k) * HW_ + xb;
            if (act)  q[k] = __ldg((const float4*)p);
            s[k] = edge ? __ldg(p + 4) : 0.0f;
        }
    };

    ldgL(LqA, LsA, 0);   // chunk 0, cc 0-7: in flight during prologue

    // Zero the left pad of sR (x<0 -> 0), both buffers, once.
    for (int idx = tid; idx < 2 * CC * 48; idx += THREADS) {
        int buf = idx / (CC * 48);
        int rem = idx - buf * (CC * 48);
        int r = rem / 48, k = rem - r * 48;
        sR[buf * (CC * RW) + r * RW + k] = 0.0f;
    }

    // accE[j]: d = i0+2j,  x pairs (xb,xb+1),(xb+2,xb+3)
    // accO[j]: d = i0+2j+1, x pairs (xb+1,xb+2),(xb+3,xb+4)
    ull accE[12][2], accO[12][2];
    #pragma unroll
    for (int j = 0; j < 12; j++) {
        accE[j][0] = 0ull; accE[j][1] = 0ull;
        accO[j][0] = 0ull; accO[j][1] = 0ull;
    }

    auto issue_load = [&](int ch, int buf) {
        const int c0 = ch * CC;
        #pragma unroll
        for (int q = 0; q < 8; q++) {            // 960 float4 tasks
            int f = tid + q * THREADS;
            if (f < 960) {
                int r = f / 60, col = (f - r * 60) * 4;
                uint32_t d = (uint32_t)__cvta_generic_to_shared(
                    &sR[buf * (CC * RW) + r * RW + 48 + col]);
                cpasync16(d, Rbase + (size_t)(c0 + r) * HW_ + col);
            }
        }
        asm volatile("cp.async.commit_group;");
    };

    // compute 8 channels from register stage (q,s) against sR rows
    // [row0, row0+8) of buffer bR.
    auto compute = [&](const float4* q, const float* s, const float* bRrows) {
        const int ab = xb - i0 + 24;
        #pragma unroll
        for (int cc = 0; cc < 8; cc++) {
            float4 Lq = q[cc];
            float  Ls = s[cc];
            ull Le0 = pk(Lq.x, Lq.y);           // aligned: elided
            ull Le1 = pk(Lq.z, Lq.w);
            ull Lo0 = pk(Lq.y, Lq.z);           // 2 MOVs
            ull Lo1 = pk(Lq.w, Ls);             // 2 MOVs

            // P[i] = (R[xb-i0-24+2i], R[xb-i0-24+2i+1]) — aligned pairs
            ull P[14];
            float2 v1 = *(const float2*)(bRrows + cc * RW + ab + 2);
            P[1] = pk(v1.x, v1.y);
            #pragma unroll
            for (int m = 0; m < 6; m++) {
                float4 qv = *(const float4*)(bRrows + cc * RW + ab + 4 + 4 * m);
                P[2*m+2] = pk(qv.x, qv.y);
                P[2*m+3] = pk(qv.z, qv.w);
            }

            #pragma unroll
            for (int j = 0; j < 12; j++) {
                fma2(accE[j][0], Le0, P[12 - j]);
                fma2(accO[j][0], Lo0, P[12 - j]);
                fma2(accE[j][1], Le1, P[13 - j]);
                fma2(accO[j][1], Lo1, P[13 - j]);
            }
        }
    };

    issue_load(0, 0);

    #pragma unroll 1
    for (int ch = 0; ch < NCH; ch++) {
        const int buf = ch & 1;
        if (ch + 1 < NCH) {
            issue_load(ch + 1, (ch + 1) & 1);
            asm volatile("cp.async.wait_group 1;");
        } else {
            asm volatile("cp.async.wait_group 0;");
        }
        __syncthreads();

        ldgL(LqB, LsB, ch * CC + 8);                 // stage B in flight
        if (act) compute(LqA, LsA, &sR[buf * (CC * RW)]);          // rows 0-7
        if (ch + 1 < NCH) ldgL(LqA, LsA, (ch + 1) * CC);           // next stage A
        if (act) compute(LqB, LsB, &sR[buf * (CC * RW) + 8 * RW]); // rows 8-15
        __syncthreads();
    }

    const float s = 1.0f / 128.0f;
    if (act) {
        #pragma unroll
        for (int j = 0; j < 12; j++) {
            const int de = i0 + 2 * j;
            float a0, a1, a2, a3;
            upk(accE[j][0], a0, a1);
            upk(accE[j][1], a2, a3);
            float4 o;
            o.x = a0 * s; o.y = a1 * s; o.z = a2 * s; o.w = a3 * s;
            *(float4*)(out + (((size_t)b * V_ + de) * H_ + h) * W_ + xb) = o;

            float b0, b1, b2, b3;
            upk(accO[j][0], b0, b1);
            upk(accO[j][1], b2, b3);
            float* oo = out + (((size_t)b * V_ + de + 1) * H_ + h) * W_ + xb;
            oo[1] = b0 * s;
            oo[2] = b1 * s;
            oo[3] = b2 * s;
            if (edge) oo[4] = b3 * s;     // x=xb+4; skip x=240 (lane 59)
        }
    } else if (xg == 60) {
        // out[x=0, odd d]: never produced by the odd pipeline; it's 0 (x<d).
        #pragma unroll
        for (int j = 0; j < 12; j++) {
            const int d = i0 + 2 * j + 1;
            out[(((size_t)b * V_ + d) * H_ + h) * W_] = 0.0f;
        }
    }
}

extern "C" void kernel_launch(void* const* d_in, const int* in_sizes, int n_in,
                              void* d_out, int out_size)
{
    const float* L = (const float*)d_in[0];
    const float* R = (const float*)d_in[1];
    float* out = (float*)d_out;

    const int smem_bytes = 2 * CC * RW * (int)sizeof(float);   // 36864
    cudaFuncSetAttribute(cv_kernel, cudaFuncAttributeMaxDynamicSharedMemorySize,
                         smem_bytes);
    cv_kernel<<<dim3(H_, B_), THREADS, smem_bytes>>>(L, R, out);
}

// round 10
// speedup vs baseline: 1.0407x; 1.0407x over previous
#include <cuda_runtime.h>
#include <cstdint>

// CostVolume: out[b,d,h,x] = (1/128) * sum_c L[b,c,h,x]*R[b,c,h,x-d], x>=d else 0
// B=8 C=128 H=128 W=240 V=48
// Tile (XT=8, IT=16): 96 threads = 3 warps, warp w owns d in [16w,16w+16).
// Parity-phased x-pairing: even-d and odd-d accumulators share the SAME
// aligned R pair registers P[i]. Swizzled smem rows make the 32B lane stride
// conflict-free; all addresses precomputed per chunk (no inner address math).
#define B_  8
#define C_  128
#define H_  128
#define W_  240
#define V_  48
#define HW_ (H_*W_)

#define CC      16            // channels per chunk
#define NCH     (C_/CC)       // 8 chunks
#define THREADS 96
#define RPITCH  1152          // R row bytes: (48 pad + 240 data)*4
#define LPITCH  1024          // L row bytes: 240*4 + 64 pad
#define RPADB   192           // R left zero pad bytes

typedef unsigned long long ull;

// XOR 128B-block bits into 16B-unit bits (row-local byte offset). Involution.
__device__ __forceinline__ uint32_t sw(uint32_t c) { return c ^ ((c >> 3) & 0x70); }

__device__ __forceinline__ ull pk(float lo, float hi) {
    ull r; asm("mov.b64 %0, {%1, %2};" : "=l"(r) : "f"(lo), "f"(hi)); return r;
}
__device__ __forceinline__ void upk(ull v, float& lo, float& hi) {
    asm("mov.b64 {%0, %1}, %2;" : "=f"(lo), "=f"(hi) : "l"(v));
}
__device__ __forceinline__ void fma2(ull& acc, ull a, ull b) {
    asm("fma.rn.f32x2 %0, %1, %2, %0;" : "+l"(acc) : "l"(a), "l"(b));
}
__device__ __forceinline__ void cpasync16(uint32_t saddr, const void* g) {
    asm volatile("cp.async.cg.shared.global [%0], [%1], 16;" :: "r"(saddr), "l"(g));
}

__global__ void __launch_bounds__(THREADS, 2)
cv_kernel(const float* __restrict__ L, const float* __restrict__ R,
          float* __restrict__ out)
{
    extern __shared__ char smem[];
    char* const smR = smem;                       // [2][CC][RPITCH]
    char* const smL = smem + 2 * CC * RPITCH;     // [2][CC][LPITCH]

    const int tid  = threadIdx.x;
    const int lane = tid & 31;
    const int w    = tid >> 5;                    // 0..2
    const int h = blockIdx.x, b = blockIdx.y;

    const int i0 = w * 16;                        // disparity base
    const int xb = lane * 8;                      // x base (lane<30 active)
    const bool act  = (lane < 30);
    const bool edge = (lane < 29);                // x = xb+8 valid

    const float* Lbase = L + ((size_t)b * C_ * H_ + h) * W_;
    const float* Rbase = R + ((size_t)b * C_ * H_ + h) * W_;

    // --- one-time pad zeroing ---
    // R rows logical [0,192): closed under sw() (blocks 0-1), zero directly.
    for (int i = tid; i < 2 * CC * 48; i += THREADS) {
        int row = i / 48, k = i - row * 48;
        *(float*)(smR + row * RPITCH + k * 4) = 0.0f;
    }
    // L rows logical [960,1024): map each word through sw().
    for (int i = tid; i < 2 * CC * 16; i += THREADS) {
        int row = i / 16, k = i - row * 16;
        *(float*)(smL + row * LPITCH + sw(960 + k * 4)) = 0.0f;
    }

    // accE[j][t]: d=i0+2j,  x pair (xb+2t, xb+2t+1)
    // accO[j][t]: d=i0+2j+1, x pair (xb+2t+1, xb+2t+2)
    // Both use R pair P[t-j+7].
    ull accE[8][4], accO[8][4];
    #pragma unroll
    for (int j = 0; j < 8; j++)
        #pragma unroll
        for (int t = 0; t < 4; t++) { accE[j][t] = 0ull; accO[j][t] = 0ull; }

    auto issue_load = [&](int ch, int buf) {
        const int c0 = ch * CC;
        #pragma unroll
        for (int q = 0; q < 20; q++) {            // 1920 float4 tasks / 96 thr
            int f = tid + q * THREADS;
            int r = f / 60, colb = (f - r * 60) * 16;   // r in [0,32)
            if (r < 16) {                         // R rows (after 48-f pad)
                uint32_t d = (uint32_t)__cvta_generic_to_shared(
                    smR + (buf * CC + r) * RPITCH) + sw(RPADB + colb);
                cpasync16(d, Rbase + (size_t)(c0 + r) * HW_ + colb / 4);
            } else {                              // L rows
                int r2 = r - 16;
                uint32_t d = (uint32_t)__cvta_generic_to_shared(
                    smL + (buf * CC + r2) * LPITCH) + sw(colb);
                cpasync16(d, Lbase + (size_t)(c0 + r2) * HW_ + colb / 4);
            }
        }
        asm volatile("cp.async.commit_group;");
    };

    // Swizzled per-row byte offsets (row-local, constant across rows/chunks).
    // R window: pairs P[i] at logical float col 48 + (xb - i0 - 14) + 2i.
    const uint32_t rb = (uint32_t)(4 * (48 + xb - i0 - 14));   // ≡ 8 mod 16
    const uint32_t rO0 = sw(rb);          // float2  (P[0])
    const uint32_t rO1 = sw(rb + 8);      // quad    (P[1],P[2])
    const uint32_t rO2 = sw(rb + 24);     // quad    (P[3],P[4])
    const uint32_t rO3 = sw(rb + 40);     // quad    (P[5],P[6])
    const uint32_t rO4 = sw(rb + 56);     // quad    (P[7],P[8])
    const uint32_t rO5 = sw(rb + 72);     // quad    (P[9],P[10])
    const uint32_t lO0 = sw((uint32_t)xb * 4);        // quad L[xb..xb+3]
    const uint32_t lO1 = sw((uint32_t)xb * 4 + 16);   // quad L[xb+4..xb+7]
    const uint32_t lO2 = sw((uint32_t)xb * 4 + 32);   // scalar L[xb+8] (padded 0)

    issue_load(0, 0);

    #pragma unroll 1
    for (int ch = 0; ch < NCH; ch++) {
        const int buf = ch & 1;
        if (ch + 1 < NCH) {
            issue_load(ch + 1, (ch + 1) & 1);
            asm volatile("cp.async.wait_group 1;");
        } else {
            asm volatile("cp.async.wait_group 0;");
        }
        __syncthreads();

        if (act) {
            const char* rrow = smR + buf * CC * RPITCH;
            const char* lrow = smL + buf * CC * LPITCH;

            #pragma unroll
            for (int cc = 0; cc < CC; cc++) {
                float4 Lq0 = *(const float4*)(lrow + cc * LPITCH + lO0);
                float4 Lq1 = *(const float4*)(lrow + cc * LPITCH + lO1);
                float  Ls  = *(const float*) (lrow + cc * LPITCH + lO2);
                ull Le0 = pk(Lq0.x, Lq0.y);       // aligned: elided
                ull Le1 = pk(Lq0.z, Lq0.w);
                ull Le2 = pk(Lq1.x, Lq1.y);
                ull Le3 = pk(Lq1.z, Lq1.w);
                ull Lo0 = pk(Lq0.y, Lq0.z);       // 8 MOVs total
                ull Lo1 = pk(Lq0.w, Lq1.x);
                ull Lo2 = pk(Lq1.y, Lq1.z);
                ull Lo3 = pk(Lq1.w, Ls);

                ull P[11];
                {
                    float2 v0 = *(const float2*)(rrow + cc * RPITCH + rO0);
                    P[0] = pk(v0.x, v0.y);
                    float4 v;
                    v = *(const float4*)(rrow + cc * RPITCH + rO1);
                    P[1] = pk(v.x, v.y); P[2] = pk(v.z, v.w);
                    v = *(const float4*)(rrow + cc * RPITCH + rO2);
                    P[3] = pk(v.x, v.y); P[4] = pk(v.z, v.w);
                    v = *(const float4*)(rrow + cc * RPITCH + rO3);
                    P[5] = pk(v.x, v.y); P[6] = pk(v.z, v.w);
                    v = *(const float4*)(rrow + cc * RPITCH + rO4);
                    P[7] = pk(v.x, v.y); P[8] = pk(v.z, v.w);
                    v = *(const float4*)(rrow + cc * RPITCH + rO5);
                    P[9] = pk(v.x, v.y); P[10] = pk(v.z, v.w);
                }

                #pragma unroll
                for (int j = 0; j < 8; j++) {
                    fma2(accE[j][0], Le0, P[0 - j + 7]);
                    fma2(accO[j][0], Lo0, P[0 - j + 7]);
                    fma2(accE[j][1], Le1, P[1 - j + 7]);
                    fma2(accO[j][1], Lo1, P[1 - j + 7]);
                    fma2(accE[j][2], Le2, P[2 - j + 7]);
                    fma2(accO[j][2], Lo2, P[2 - j + 7]);
                    fma2(accE[j][3], Le3, P[3 - j + 7]);
                    fma2(accO[j][3], Lo3, P[3 - j + 7]);
                }
            }
        }
        __syncthreads();
    }

    const float s = 1.0f / 128.0f;
    if (act) {
        #pragma unroll
        for (int j = 0; j < 8; j++) {
            // even d: aligned x in [xb, xb+8)
            const int de = i0 + 2 * j;
            float e0,e1,e2,e3,e4,e5,e6,e7;
            upk(accE[j][0], e0, e1);
            upk(accE[j][1], e2, e3);
            upk(accE[j][2], e4, e5);
            upk(accE[j][3], e6, e7);
            float* oe = out + (((size_t)b * V_ + de) * H_ + h) * W_ + xb;
            float4 o0, o1;
            o0.x=e0*s; o0.y=e1*s; o0.z=e2*s; o0.w=e3*s;
            o1.x=e4*s; o1.y=e5*s; o1.z=e6*s; o1.w=e7*s;
            *(float4*)(oe)     = o0;
            *(float4*)(oe + 4) = o1;

            // odd d: x in [xb+1, xb+8]
            float q0,q1,q2,q3,q4,q5,q6,q7;
            upk(accO[j][0], q0, q1);
            upk(accO[j][1], q2, q3);
            upk(accO[j][2], q4, q5);
            upk(accO[j][3], q6, q7);
            float* oo = out + (((size_t)b * V_ + de + 1) * H_ + h) * W_ + xb;
            oo[1] = q0*s; oo[2] = q1*s; oo[3] = q2*s; oo[4] = q3*s;
            oo[5] = q4*s; oo[6] = q5*s; oo[7] = q6*s;
            if (edge) oo[8] = q7*s;      // x=xb+8; lane 29 skips x=240
        }
    } else if (lane == 30) {
        // out[x=0, odd d] for this warp's d-group: 0 (x < d).
        #pragma unroll
        for (int j = 0; j < 8; j++) {
            const int d = i0 + 2 * j + 1;
            out[(((size_t)b * V_ + d) * H_ + h) * W_] = 0.0f;
        }
    }
}

extern "C" void kernel_launch(void* const* d_in, const int* in_sizes, int n_in,
                              void* d_out, int out_size)
{
    const float* L = (const float*)d_in[0];
    const float* R = (const float*)d_in[1];
    float* out = (float*)d_out;

    const int smem_bytes = 2 * CC * RPITCH + 2 * CC * LPITCH;  // 69632
    cudaFuncSetAttribute(cv_kernel, cudaFuncAttributeMaxDynamicSharedMemorySize,
                         smem_bytes);
    cv_kernel<<<dim3(H_, B_), THREADS, smem_bytes>>>(L, R, out);
}

// round 11
// speedup vs baseline: 1.6971x; 1.6308x over previous
#include <cuda_runtime.h>
#include <cstdint>

// CostVolume: out[b,d,h,x] = (1/128) * sum_c L[b,c,h,x]*R[b,c,h,x-d], x>=d else 0
// B=8 C=128 H=128 W=240 V=48
// R7 tile (XT=4, IT=24, parity-phased pairing) + explicit register
// double-buffering of smem operands + division-free cp.async loader.
#define B_  8
#define C_  128
#define H_  128
#define W_  240
#define V_  48
#define HW_ (H_*W_)

#define CC   16            // channels per chunk
#define NCH  (C_/CC)       // 8 chunks
#define THREADS 128
#define RW   288           // sR row width: 48 zero pad + 240 data

typedef unsigned long long ull;

__device__ __forceinline__ ull pk(float lo, float hi) {
    ull r; asm("mov.b64 %0, {%1, %2};" : "=l"(r) : "f"(lo), "f"(hi)); return r;
}
__device__ __forceinline__ void upk(ull v, float& lo, float& hi) {
    asm("mov.b64 {%0, %1}, %2;" : "=f"(lo), "=f"(hi) : "l"(v));
}
__device__ __forceinline__ void fma2(ull& acc, ull a, ull b) {
    asm("fma.rn.f32x2 %0, %1, %2, %0;" : "+l"(acc) : "l"(a), "l"(b));
}
__device__ __forceinline__ void cpasync16(uint32_t saddr, const void* g) {
    asm volatile("cp.async.cg.shared.global [%0], [%1], 16;" :: "r"(saddr), "l"(g));
}

struct Stage {
    float4 Lq; float Ls;
    float2 r0;
    float4 r1, r2, r3, r4, r5, r6;
};

__global__ void __launch_bounds__(THREADS, 2)
cv_kernel(const float* __restrict__ L, const float* __restrict__ R,
          float* __restrict__ out)
{
    extern __shared__ float smem[];
    float* sL = smem;                 // [2][CC][W_]
    float* sR = smem + 2 * CC * W_;   // [2][CC][RW]

    const int tid = threadIdx.x;
    const int h = blockIdx.x;
    const int b = blockIdx.y;

    const int xg = tid & 63;          // 0..63 (60 active)
    const int ig = tid >> 6;          // 0..1
    const int i0 = ig * 24;           // disparity base
    const int xb = xg * 4;
    const bool act  = (xg < 60);
    const bool edge = (xg < 59);

    const float* Lbase = L + ((size_t)b * C_ * H_ + h) * W_;
    const float* Rbase = R + ((size_t)b * C_ * H_ + h) * W_;

    // Zero the left pad of sR (x<0 -> 0), both buffers, once.
    for (int idx = tid; idx < 2 * CC * 48; idx += THREADS) {
        int buf = idx / (CC * 48);
        int rem = idx - buf * (CC * 48);
        int r = rem / 48, k = rem - r * 48;
        sR[buf * (CC * RW) + r * RW + k] = 0.0f;
    }

    // --- division-free loader: thread<120 owns (row0, col); rows row0+2k ---
    const bool loader = (tid < 120);
    const int lr0  = (tid >= 60) ? 1 : 0;
    const int lcol = tid - lr0 * 60;             // 0..59 (quad index)
    const float* gL = Lbase + (size_t)lr0 * HW_ + lcol * 4;
    const float* gR = Rbase + (size_t)lr0 * HW_ + lcol * 4;
    const uint32_t sLb = (uint32_t)__cvta_generic_to_shared(sL)
                       + (uint32_t)(lr0 * W_ + lcol * 4) * 4;
    const uint32_t sRb = (uint32_t)__cvta_generic_to_shared(sR)
                       + (uint32_t)(lr0 * RW + 48 + lcol * 4) * 4;

    auto issue_load = [&](int buf) {
        if (loader) {
            const uint32_t dL = sLb + (uint32_t)buf * (CC * W_ * 4);
            const uint32_t dR = sRb + (uint32_t)buf * (CC * RW * 4);
            #pragma unroll
            for (int k = 0; k < 8; k++) {        // rows lr0 + 2k
                cpasync16(dL + k * (2 * W_ * 4), gL + (size_t)k * 2 * HW_);
                cpasync16(dR + k * (2 * RW * 4), gR + (size_t)k * 2 * HW_);
            }
        }
        asm volatile("cp.async.commit_group;");
    };

    // accE[j]: d=i0+2j,  x pairs (xb,xb+1),(xb+2,xb+3)
    // accO[j]: d=i0+2j+1, x pairs (xb+1,xb+2),(xb+3,xb+4)
    ull accE[12][2], accO[12][2];
    #pragma unroll
    for (int j = 0; j < 12; j++) {
        accE[j][0] = 0ull; accE[j][1] = 0ull;
        accO[j][0] = 0ull; accO[j][1] = 0ull;
    }

    issue_load(0);
    gL += CC * HW_; gR += CC * HW_;

    #pragma unroll 1
    for (int ch = 0; ch < NCH; ch++) {
        const int buf = ch & 1;
        if (ch + 1 < NCH) {
            issue_load((ch + 1) & 1);
            gL += CC * HW_; gR += CC * HW_;
            asm volatile("cp.async.wait_group 1;");
        } else {
            asm volatile("cp.async.wait_group 0;");
        }
        __syncthreads();

        if (act) {
            const float* lw = &sL[buf * (CC * W_)] + xb;          // L row base
            const float* rw = &sR[buf * (CC * RW)] + (xb - i0 + 24); // window base
            Stage SA, SB;

            // stage load for channel cc (compile-time cc)
            #define LDS_STAGE(S, cc) do {                                   \
                (S).Lq = *(const float4*)(lw + (cc) * W_);                  \
                (S).Ls = lw[(cc) * W_ + 4];                                 \
                (S).r0 = *(const float2*)(rw + (cc) * RW + 2);              \
                (S).r1 = *(const float4*)(rw + (cc) * RW + 4);              \
                (S).r2 = *(const float4*)(rw + (cc) * RW + 8);              \
                (S).r3 = *(const float4*)(rw + (cc) * RW + 12);             \
                (S).r4 = *(const float4*)(rw + (cc) * RW + 16);             \
                (S).r5 = *(const float4*)(rw + (cc) * RW + 20);             \
                (S).r6 = *(const float4*)(rw + (cc) * RW + 24);             \
            } while (0)

            #define FMA_STAGE(S) do {                                       \
                ull Le0 = pk((S).Lq.x, (S).Lq.y);                           \
                ull Le1 = pk((S).Lq.z, (S).Lq.w);                           \
                ull Lo0 = pk((S).Lq.y, (S).Lq.z);                           \
                ull Lo1 = pk((S).Lq.w, (S).Ls);                             \
                ull P[14];                                                  \
                P[1]  = pk((S).r0.x, (S).r0.y);                             \
                P[2]  = pk((S).r1.x, (S).r1.y); P[3]  = pk((S).r1.z, (S).r1.w); \
                P[4]  = pk((S).r2.x, (S).r2.y); P[5]  = pk((S).r2.z, (S).r2.w); \
                P[6]  = pk((S).r3.x, (S).r3.y); P[7]  = pk((S).r3.z, (S).r3.w); \
                P[8]  = pk((S).r4.x, (S).r4.y); P[9]  = pk((S).r4.z, (S).r4.w); \
                P[10] = pk((S).r5.x, (S).r5.y); P[11] = pk((S).r5.z, (S).r5.w); \
                P[12] = pk((S).r6.x, (S).r6.y); P[13] = pk((S).r6.z, (S).r6.w); \
                _Pragma("unroll")                                           \
                for (int j = 0; j < 12; j++) {                              \
                    fma2(accE[j][0], Le0, P[12 - j]);                       \
                    fma2(accO[j][0], Lo0, P[12 - j]);                       \
                    fma2(accE[j][1], Le1, P[13 - j]);                       \
                    fma2(accO[j][1], Lo1, P[13 - j]);                       \
                }                                                           \
            } while (0)

            LDS_STAGE(SA, 0);
            #pragma unroll
            for (int cc = 0; cc < CC; cc += 2) {
                if (cc + 1 < CC) LDS_STAGE(SB, cc + 1);
                FMA_STAGE(SA);
                if (cc + 2 < CC) LDS_STAGE(SA, cc + 2);
                if (cc + 1 < CC) FMA_STAGE(SB);
            }
            #undef LDS_STAGE
            #undef FMA_STAGE
        }
        __syncthreads();
    }

    const float s = 1.0f / 128.0f;
    if (act) {
        #pragma unroll
        for (int j = 0; j < 12; j++) {
            const int de = i0 + 2 * j;
            float a0, a1, a2, a3;
            upk(accE[j][0], a0, a1);
            upk(accE[j][1], a2, a3);
            float4 o;
            o.x = a0 * s; o.y = a1 * s; o.z = a2 * s; o.w = a3 * s;
            *(float4*)(out + (((size_t)b * V_ + de) * H_ + h) * W_ + xb) = o;

            float b0, b1, b2, b3;
            upk(accO[j][0], b0, b1);
            upk(accO[j][1], b2, b3);
            float* oo = out + (((size_t)b * V_ + de + 1) * H_ + h) * W_ + xb;
            oo[1] = b0 * s;
            oo[2] = b1 * s;
            oo[3] = b2 * s;
            if (edge) oo[4] = b3 * s;     // x=xb+4; lane xg=59 skips x=240
        }
    } else if (xg == 60) {
        // out[x=0, odd d]: never produced by the odd pipeline; it's 0 (x<d).
        #pragma unroll
        for (int j = 0; j < 12; j++) {
            const int d = i0 + 2 * j + 1;
            out[(((size_t)b * V_ + d) * H_ + h) * W_] = 0.0f;
        }
    }
}

extern "C" void kernel_launch(void* const* d_in, const int* in_sizes, int n_in,
                              void* d_out, int out_size)
{
    const float* L = (const float*)d_in[0];
    const float* R = (const float*)d_in[1];
    float* out = (float*)d_out;

    const int smem_bytes = (2 * CC * W_ + 2 * CC * RW) * (int)sizeof(float); // 67584
    cudaFuncSetAttribute(cv_kernel, cudaFuncAttributeMaxDynamicSharedMemorySize,
                         smem_bytes);
    cv_kernel<<<dim3(H_, B_), THREADS, smem_bytes>>>(L, R, out);
}